// round 1
// baseline (speedup 1.0000x reference)
#include <cuda_runtime.h>
#include <cstdint>

#define NN 4096
#define EE 8192
#define FDIM 64   // FIN == FOUT == 64
#define BN_EPS 1e-5f

// ---------------- device scratch (no allocations allowed) ----------------
__device__ float g_pd_y[NN * FDIM];   // pd @ y           [N,64]
__device__ float g_x[NN * FDIM];      // x (pre/post BN)  [N,64]
__device__ float g_lg_y[EE * FDIM];   // lg_a1 @ y        [E,64]
__device__ float g_pm_x[EE * FDIM];   // pm^T @ x         [E,64]
__device__ float g_stats[256];        // [0:64) xsum [64:128) xsq [128:192) ysum [192:256) ysq

// ---------------- zero scratch ----------------
__global__ void k_zero() {
    int idx = blockIdx.x * blockDim.x + threadIdx.x;
    if (idx < EE * FDIM) g_pm_x[idx] = 0.f;
    if (idx < 256) g_stats[idx] = 0.f;
}

// ---------------- sparse-from-dense gather SpMM ----------------
__device__ __forceinline__ unsigned nz4(float4 v) {
    return __float_as_uint(v.x) | __float_as_uint(v.y) |
           __float_as_uint(v.z) | __float_as_uint(v.w);
}

__device__ __forceinline__ void gath_chunk(float4 v, unsigned ored, int colbase, int lane,
                                           const float* __restrict__ B,
                                           float& acc0, float& acc1) {
    unsigned mask = __ballot_sync(0xffffffffu, ored != 0u);
    while (mask) {
        int src = __ffs(mask) - 1;
        mask &= mask - 1;
        float b0 = __shfl_sync(0xffffffffu, v.x, src);
        float b1 = __shfl_sync(0xffffffffu, v.y, src);
        float b2 = __shfl_sync(0xffffffffu, v.z, src);
        float b3 = __shfl_sync(0xffffffffu, v.w, src);
        const float* bp = B + (size_t)(colbase + (src << 2)) * FDIM + lane;
        if (b0 != 0.f) { acc0 = fmaf(b0, bp[0],   acc0); acc1 = fmaf(b0, bp[32],  acc1); }
        if (b1 != 0.f) { acc0 = fmaf(b1, bp[64],  acc0); acc1 = fmaf(b1, bp[96],  acc1); }
        if (b2 != 0.f) { acc0 = fmaf(b2, bp[128], acc0); acc1 = fmaf(b2, bp[160], acc1); }
        if (b3 != 0.f) { acc0 = fmaf(b3, bp[192], acc0); acc1 = fmaf(b3, bp[224], acc1); }
    }
}

// out[r,:] = sum_c A[r,c] * B[c,:]   (A: rows x cols dense 0/1-ish, B: cols x 64)
__global__ __launch_bounds__(256) void k_spmm_gather(const float* __restrict__ A,
                                                     const float* __restrict__ B,
                                                     float* __restrict__ out,
                                                     int rows, int cols) {
    int gw = (blockIdx.x * blockDim.x + threadIdx.x) >> 5;
    int lane = threadIdx.x & 31;
    if (gw >= rows) return;
    const float4* arow = reinterpret_cast<const float4*>(A + (size_t)gw * cols);
    float acc0 = 0.f, acc1 = 0.f;
    int groups = cols >> 9;  // 512 floats (= 128 float4) per group
    for (int g = 0; g < groups; ++g) {
        int fb = g << 7;  // float4 index base
        float4 v0 = __ldg(arow + fb + lane);
        float4 v1 = __ldg(arow + fb + 32 + lane);
        float4 v2 = __ldg(arow + fb + 64 + lane);
        float4 v3 = __ldg(arow + fb + 96 + lane);
        unsigned o0 = nz4(v0), o1 = nz4(v1), o2 = nz4(v2), o3 = nz4(v3);
        if (__ballot_sync(0xffffffffu, (o0 | o1 | o2 | o3) != 0u)) {
            int cb = g << 9;
            gath_chunk(v0, o0, cb,       lane, B, acc0, acc1);
            gath_chunk(v1, o1, cb + 128, lane, B, acc0, acc1);
            gath_chunk(v2, o2, cb + 256, lane, B, acc0, acc1);
            gath_chunk(v3, o3, cb + 384, lane, B, acc0, acc1);
        }
    }
    out[(size_t)gw * FDIM + lane]      = acc0;
    out[(size_t)gw * FDIM + lane + 32] = acc1;
}

// ---------------- pm^T @ x_bn scatter ----------------
__device__ __forceinline__ void scat_chunk(float4 v, unsigned ored, int colbase, int lane,
                                           float x0, float x1) {
    unsigned mask = __ballot_sync(0xffffffffu, ored != 0u);
    while (mask) {
        int src = __ffs(mask) - 1;
        mask &= mask - 1;
        float b0 = __shfl_sync(0xffffffffu, v.x, src);
        float b1 = __shfl_sync(0xffffffffu, v.y, src);
        float b2 = __shfl_sync(0xffffffffu, v.z, src);
        float b3 = __shfl_sync(0xffffffffu, v.w, src);
        int col = colbase + (src << 2);
        if (b0 != 0.f) { atomicAdd(&g_pm_x[(size_t)col * FDIM + lane], b0 * x0);
                         atomicAdd(&g_pm_x[(size_t)col * FDIM + lane + 32], b0 * x1); }
        if (b1 != 0.f) { atomicAdd(&g_pm_x[(size_t)(col + 1) * FDIM + lane], b1 * x0);
                         atomicAdd(&g_pm_x[(size_t)(col + 1) * FDIM + lane + 32], b1 * x1); }
        if (b2 != 0.f) { atomicAdd(&g_pm_x[(size_t)(col + 2) * FDIM + lane], b2 * x0);
                         atomicAdd(&g_pm_x[(size_t)(col + 2) * FDIM + lane + 32], b2 * x1); }
        if (b3 != 0.f) { atomicAdd(&g_pm_x[(size_t)(col + 3) * FDIM + lane], b3 * x0);
                         atomicAdd(&g_pm_x[(size_t)(col + 3) * FDIM + lane + 32], b3 * x1); }
    }
}

__global__ __launch_bounds__(256) void k_pm_scatter(const float* __restrict__ A,
                                                    int rows, int cols) {
    int gw = (blockIdx.x * blockDim.x + threadIdx.x) >> 5;
    int lane = threadIdx.x & 31;
    if (gw >= rows) return;
    float x0 = g_x[(size_t)gw * FDIM + lane];
    float x1 = g_x[(size_t)gw * FDIM + lane + 32];
    const float4* arow = reinterpret_cast<const float4*>(A + (size_t)gw * cols);
    int groups = cols >> 9;
    for (int g = 0; g < groups; ++g) {
        int fb = g << 7;
        float4 v0 = __ldg(arow + fb + lane);
        float4 v1 = __ldg(arow + fb + 32 + lane);
        float4 v2 = __ldg(arow + fb + 64 + lane);
        float4 v3 = __ldg(arow + fb + 96 + lane);
        unsigned o0 = nz4(v0), o1 = nz4(v1), o2 = nz4(v2), o3 = nz4(v3);
        if (__ballot_sync(0xffffffffu, (o0 | o1 | o2 | o3) != 0u)) {
            int cb = g << 9;
            scat_chunk(v0, o0, cb,       lane, x0, x1);
            scat_chunk(v1, o1, cb + 128, lane, x0, x1);
            scat_chunk(v2, o2, cb + 256, lane, x0, x1);
            scat_chunk(v3, o3, cb + 384, lane, x0, x1);
        }
    }
}

// ---------------- x = concat(pd_y@W^T+b, relu(pd_y@Wr^T+br)), + BN stats ----------------
__global__ __launch_bounds__(256) void k_x_linear(const float* __restrict__ tw,
                                                  const float* __restrict__ tb,
                                                  const float* __restrict__ trw,
                                                  const float* __restrict__ trb) {
    __shared__ float s_in[16 * 64];
    __shared__ float red[256], red2[256];
    int t = threadIdx.x;
    int rowbase = blockIdx.x * 16;
    reinterpret_cast<float4*>(s_in)[t] =
        reinterpret_cast<const float4*>(g_pd_y + (size_t)rowbase * 64)[t];
    __syncthreads();
    int c = t & 63, slot = t >> 6;
    const float* w; float bias; bool dorelu;
    if (c < 32) { w = tw + c * 64;        bias = tb[c];       dorelu = false; }
    else        { w = trw + (c - 32) * 64; bias = trb[c - 32]; dorelu = true; }
    float acc[4] = {bias, bias, bias, bias};
    #pragma unroll
    for (int f = 0; f < 64; f += 4) {
        float4 wv = *reinterpret_cast<const float4*>(w + f);
        #pragma unroll
        for (int j = 0; j < 4; ++j) {
            float4 pv = *reinterpret_cast<const float4*>(&s_in[(slot + 4 * j) * 64 + f]);
            acc[j] = fmaf(wv.x, pv.x, fmaf(wv.y, pv.y, fmaf(wv.z, pv.z, fmaf(wv.w, pv.w, acc[j]))));
        }
    }
    float s = 0.f, sq = 0.f;
    #pragma unroll
    for (int j = 0; j < 4; ++j) {
        float v = acc[j];
        if (dorelu) v = fmaxf(v, 0.f);
        g_x[(size_t)(rowbase + slot + 4 * j) * 64 + c] = v;
        s += v; sq += v * v;
    }
    red[t] = s; red2[t] = sq;
    __syncthreads();
    if (slot == 0) {
        atomicAdd(&g_stats[c],      red[c] + red[64 + c] + red[128 + c] + red[192 + c]);
        atomicAdd(&g_stats[64 + c], red2[c] + red2[64 + c] + red2[128 + c] + red2[192 + c]);
    }
}

// ---------------- y_out = concat(lin, relu(lin_r)) from lg_y + pm_x, + BN stats ----------------
__global__ __launch_bounds__(256) void k_y_linear(const float* __restrict__ gaw,
                                                  const float* __restrict__ gab,
                                                  const float* __restrict__ gxw,
                                                  const float* __restrict__ gxb,
                                                  const float* __restrict__ garw,
                                                  const float* __restrict__ garb,
                                                  const float* __restrict__ gxrw,
                                                  const float* __restrict__ gxrb,
                                                  float* __restrict__ out) {
    __shared__ float s_lg[16 * 64];
    __shared__ float s_pm[16 * 64];
    __shared__ float red[256], red2[256];
    int t = threadIdx.x;
    int rowbase = blockIdx.x * 16;
    reinterpret_cast<float4*>(s_lg)[t] =
        reinterpret_cast<const float4*>(g_lg_y + (size_t)rowbase * 64)[t];
    reinterpret_cast<float4*>(s_pm)[t] =
        reinterpret_cast<const float4*>(g_pm_x + (size_t)rowbase * 64)[t];
    __syncthreads();
    int c = t & 63, slot = t >> 6;
    const float *wa, *wx; float bias; bool dorelu;
    if (c < 32) { wa = gaw + c * 64;  wx = gxw + c * 64;
                  bias = gab[c] + gxb[c];           dorelu = false; }
    else        { int cr = c - 32;
                  wa = garw + cr * 64; wx = gxrw + cr * 64;
                  bias = garb[cr] + gxrb[cr];       dorelu = true; }
    float acc[4] = {bias, bias, bias, bias};
    #pragma unroll
    for (int f = 0; f < 64; f += 4) {
        float4 wav = *reinterpret_cast<const float4*>(wa + f);
        float4 wxv = *reinterpret_cast<const float4*>(wx + f);
        #pragma unroll
        for (int j = 0; j < 4; ++j) {
            float4 pa = *reinterpret_cast<const float4*>(&s_lg[(slot + 4 * j) * 64 + f]);
            float4 px = *reinterpret_cast<const float4*>(&s_pm[(slot + 4 * j) * 64 + f]);
            float a = acc[j];
            a = fmaf(wav.x, pa.x, fmaf(wav.y, pa.y, fmaf(wav.z, pa.z, fmaf(wav.w, pa.w, a))));
            a = fmaf(wxv.x, px.x, fmaf(wxv.y, px.y, fmaf(wxv.z, px.z, fmaf(wxv.w, px.w, a))));
            acc[j] = a;
        }
    }
    float s = 0.f, sq = 0.f;
    #pragma unroll
    for (int j = 0; j < 4; ++j) {
        float v = acc[j];
        if (dorelu) v = fmaxf(v, 0.f);
        out[(size_t)(rowbase + slot + 4 * j) * 64 + c] = v;
        s += v; sq += v * v;
    }
    red[t] = s; red2[t] = sq;
    __syncthreads();
    if (slot == 0) {
        atomicAdd(&g_stats[128 + c], red[c] + red[64 + c] + red[128 + c] + red[192 + c]);
        atomicAdd(&g_stats[192 + c], red2[c] + red2[64 + c] + red2[128 + c] + red2[192 + c]);
    }
}

// ---------------- BN apply (in place) ----------------
__global__ __launch_bounds__(256) void k_bn_apply(float* __restrict__ buf,
                                                  const float* __restrict__ w,
                                                  const float* __restrict__ b,
                                                  int statoff, float invn, int total) {
    int idx = blockIdx.x * blockDim.x + threadIdx.x;
    if (idx >= total) return;
    int c = idx & 63;
    float m = g_stats[statoff + c] * invn;
    float var = g_stats[statoff + 64 + c] * invn - m * m;
    float sc = w[c] * rsqrtf(var + BN_EPS);
    buf[idx] = (buf[idx] - m) * sc + b[c];
}

// ---------------- launch ----------------
extern "C" void kernel_launch(void* const* d_in, const int* in_sizes, int n_in,
                              void* d_out, int out_size) {
    const float* y    = (const float*)d_in[0];
    const float* lg   = (const float*)d_in[3];
    const float* pm   = (const float*)d_in[4];
    const float* pd   = (const float*)d_in[5];
    const float* tw   = (const float*)d_in[6];
    const float* tb   = (const float*)d_in[7];
    const float* trw  = (const float*)d_in[8];
    const float* trb  = (const float*)d_in[9];
    const float* gaw  = (const float*)d_in[10];
    const float* gab  = (const float*)d_in[11];
    const float* gxw  = (const float*)d_in[12];
    const float* gxb  = (const float*)d_in[13];
    const float* garw = (const float*)d_in[14];
    const float* garb = (const float*)d_in[15];
    const float* gxrw = (const float*)d_in[16];
    const float* gxrb = (const float*)d_in[17];
    const float* bxw  = (const float*)d_in[18];
    const float* bxb  = (const float*)d_in[19];
    const float* byw  = (const float*)d_in[20];
    const float* byb  = (const float*)d_in[21];
    float* out = (float*)d_out;

    float *p_pdy = nullptr, *p_lgy = nullptr, *p_x = nullptr;
    cudaGetSymbolAddress((void**)&p_pdy, g_pd_y);
    cudaGetSymbolAddress((void**)&p_lgy, g_lg_y);
    cudaGetSymbolAddress((void**)&p_x,   g_x);

    k_zero<<<2048, 256>>>();
    // pd @ y : [N,64]   (128 MB stream)
    k_spmm_gather<<<NN / 8, 256>>>(pd, y, p_pdy, NN, EE);
    // x linear + concat/relu + BN stats
    k_x_linear<<<NN / 16, 256>>>(tw, tb, trw, trb);
    // BN x (in place on g_x)
    k_bn_apply<<<(NN * FDIM) / 256, 256>>>(p_x, bxw, bxb, 0, 1.f / NN, NN * FDIM);
    // lg_a1 @ y : [E,64]  (256 MB stream)
    k_spmm_gather<<<EE / 8, 256>>>(lg, y, p_lgy, EE, EE);
    // pm^T @ x_bn : [E,64] (128 MB stream, atomic scatter)
    k_pm_scatter<<<NN / 8, 256>>>(pm, NN, EE);
    // y combine + concat/relu + BN stats -> d_out (pre-BN)
    k_y_linear<<<EE / 16, 256>>>(gaw, gab, gxw, gxb, garw, garb, gxrw, gxrb, out);
    // BN y (in place on d_out)
    k_bn_apply<<<(EE * FDIM) / 256, 256>>>(out, byw, byb, 128, 1.f / EE, EE * FDIM);
}

// round 2
// speedup vs baseline: 1.0333x; 1.0333x over previous
#include <cuda_runtime.h>
#include <cstdint>

#define NN 4096
#define EE 8192
#define FDIM 64
#define BN_EPS 1e-5f
#define TRIP_CAP 131072   // pm expected nnz ~16384; 8x headroom

// ---------------- device scratch ----------------
__device__ float g_pd_y[NN * FDIM];   // pd @ y           [N,64]
__device__ float g_x[NN * FDIM];      // x pre-BN (post-relu concat) [N,64]
__device__ float g_lg_y[EE * FDIM];   // lg_a1 @ y        [E,64]
__device__ float g_pm_x[EE * FDIM];   // pm^T @ x_bn      [E,64]
__device__ float g_stats[256];        // xsum/xsq/ysum/ysq (64 each)
__device__ int   g_cnt;               // pm triplet count
__device__ int   g_trip_n[TRIP_CAP];
__device__ int   g_trip_e[TRIP_CAP];
__device__ float g_trip_v[TRIP_CAP];

// ---------------- init: zero pm_x, stats, counter ----------------
__global__ __launch_bounds__(256) void k_init() {
    int idx = blockIdx.x * 256 + threadIdx.x;              // 512*256 = 131072
    reinterpret_cast<float4*>(g_pm_x)[idx] = make_float4(0.f, 0.f, 0.f, 0.f);
    if (idx < 256) g_stats[idx] = 0.f;
    if (idx == 0) g_cnt = 0;
}

// ---------------- helpers ----------------
__device__ __forceinline__ unsigned nz4(float4 v) {
    return __float_as_uint(v.x) | __float_as_uint(v.y) |
           __float_as_uint(v.z) | __float_as_uint(v.w);
}

__device__ __forceinline__ void gath_chunk(float4 v, unsigned ored, int colbase, int lane,
                                           const float* __restrict__ B,
                                           float& acc0, float& acc1) {
    unsigned mask = __ballot_sync(0xffffffffu, ored != 0u);
    while (mask) {
        int src = __ffs(mask) - 1;
        mask &= mask - 1;
        float b0 = __shfl_sync(0xffffffffu, v.x, src);
        float b1 = __shfl_sync(0xffffffffu, v.y, src);
        float b2 = __shfl_sync(0xffffffffu, v.z, src);
        float b3 = __shfl_sync(0xffffffffu, v.w, src);
        const float* bp = B + (size_t)(colbase + (src << 2)) * FDIM + lane;
        if (b0 != 0.f) { acc0 = fmaf(b0, bp[0],   acc0); acc1 = fmaf(b0, bp[32],  acc1); }
        if (b1 != 0.f) { acc0 = fmaf(b1, bp[64],  acc0); acc1 = fmaf(b1, bp[96],  acc1); }
        if (b2 != 0.f) { acc0 = fmaf(b2, bp[128], acc0); acc1 = fmaf(b2, bp[160], acc1); }
        if (b3 != 0.f) { acc0 = fmaf(b3, bp[192], acc0); acc1 = fmaf(b3, bp[224], acc1); }
    }
}

__device__ __forceinline__ void pm_emit(float4 v, int col0, int n) {
    int k = (v.x != 0.f) + (v.y != 0.f) + (v.z != 0.f) + (v.w != 0.f);
    if (!k) return;
    int pos = atomicAdd(&g_cnt, k);
    float vals[4] = {v.x, v.y, v.z, v.w};
    #pragma unroll
    for (int j = 0; j < 4; ++j) {
        if (vals[j] != 0.f && pos < TRIP_CAP) {
            g_trip_n[pos] = n;
            g_trip_e[pos] = col0 + j;
            g_trip_v[pos] = vals[j];
            ++pos;
        }
    }
}

// ---------------- mega-scan: pd gather | lg gather | pm triplet extract ----------------
// 16384 warps, one per 8192-float row. pd rows [0,4096), lg rows [4096,12288),
// pm rows [12288,16384).
__global__ __launch_bounds__(256) void k_megascan(const float* __restrict__ pd,
                                                  const float* __restrict__ lg,
                                                  const float* __restrict__ pm,
                                                  const float* __restrict__ y) {
    int gw = (blockIdx.x * 256 + threadIdx.x) >> 5;
    int lane = threadIdx.x & 31;

    const float4* arow;
    int mode, row;
    if (gw < NN)            { mode = 0; row = gw;            arow = reinterpret_cast<const float4*>(pd + (size_t)row * EE); }
    else if (gw < NN + EE)  { mode = 1; row = gw - NN;       arow = reinterpret_cast<const float4*>(lg + (size_t)row * EE); }
    else                    { mode = 2; row = gw - NN - EE;  arow = reinterpret_cast<const float4*>(pm + (size_t)row * EE); }

    if (mode < 2) {
        float acc0 = 0.f, acc1 = 0.f;
        #pragma unroll 1
        for (int g = 0; g < EE / 512; ++g) {
            int fb = g << 7;
            float4 v0 = __ldg(arow + fb + lane);
            float4 v1 = __ldg(arow + fb + 32 + lane);
            float4 v2 = __ldg(arow + fb + 64 + lane);
            float4 v3 = __ldg(arow + fb + 96 + lane);
            unsigned o0 = nz4(v0), o1 = nz4(v1), o2 = nz4(v2), o3 = nz4(v3);
            if (__ballot_sync(0xffffffffu, (o0 | o1 | o2 | o3) != 0u)) {
                int cb = g << 9;
                gath_chunk(v0, o0, cb,       lane, y, acc0, acc1);
                gath_chunk(v1, o1, cb + 128, lane, y, acc0, acc1);
                gath_chunk(v2, o2, cb + 256, lane, y, acc0, acc1);
                gath_chunk(v3, o3, cb + 384, lane, y, acc0, acc1);
            }
        }
        float* out = (mode == 0 ? g_pd_y : g_lg_y) + (size_t)row * FDIM;
        out[lane]      = acc0;
        out[lane + 32] = acc1;
    } else {
        #pragma unroll 1
        for (int g = 0; g < EE / 512; ++g) {
            int fb = g << 7;
            float4 v0 = __ldg(arow + fb + lane);
            float4 v1 = __ldg(arow + fb + 32 + lane);
            float4 v2 = __ldg(arow + fb + 64 + lane);
            float4 v3 = __ldg(arow + fb + 96 + lane);
            unsigned o0 = nz4(v0), o1 = nz4(v1), o2 = nz4(v2), o3 = nz4(v3);
            if (__ballot_sync(0xffffffffu, (o0 | o1 | o2 | o3) != 0u)) {
                int cb = g << 9;
                int lb = lane << 2;
                pm_emit(v0, cb + lb,       row);
                pm_emit(v1, cb + 128 + lb, row);
                pm_emit(v2, cb + 256 + lb, row);
                pm_emit(v3, cb + 384 + lb, row);
            }
        }
    }
}

// ---------------- x = concat(lin, relu(lin_r)) from pd_y, + BN stats ----------------
__global__ __launch_bounds__(256) void k_x_linear(const float* __restrict__ tw,
                                                  const float* __restrict__ tb,
                                                  const float* __restrict__ trw,
                                                  const float* __restrict__ trb) {
    __shared__ float s_in[16 * 64];
    __shared__ float red[256], red2[256];
    int t = threadIdx.x;
    int rowbase = blockIdx.x * 16;
    reinterpret_cast<float4*>(s_in)[t] =
        reinterpret_cast<const float4*>(g_pd_y + (size_t)rowbase * 64)[t];
    __syncthreads();
    int c = t & 63, slot = t >> 6;
    const float* w; float bias; bool dorelu;
    if (c < 32) { w = tw + c * 64;         bias = tb[c];        dorelu = false; }
    else        { w = trw + (c - 32) * 64; bias = trb[c - 32];  dorelu = true;  }
    float acc[4] = {bias, bias, bias, bias};
    #pragma unroll
    for (int f = 0; f < 64; f += 4) {
        float4 wv = *reinterpret_cast<const float4*>(w + f);
        #pragma unroll
        for (int j = 0; j < 4; ++j) {
            float4 pv = *reinterpret_cast<const float4*>(&s_in[(slot + 4 * j) * 64 + f]);
            acc[j] = fmaf(wv.x, pv.x, fmaf(wv.y, pv.y, fmaf(wv.z, pv.z, fmaf(wv.w, pv.w, acc[j]))));
        }
    }
    float s = 0.f, sq = 0.f;
    #pragma unroll
    for (int j = 0; j < 4; ++j) {
        float v = acc[j];
        if (dorelu) v = fmaxf(v, 0.f);
        g_x[(size_t)(rowbase + slot + 4 * j) * 64 + c] = v;
        s += v; sq += v * v;
    }
    red[t] = s; red2[t] = sq;
    __syncthreads();
    if (slot == 0) {
        atomicAdd(&g_stats[c],      red[c] + red[64 + c] + red[128 + c] + red[192 + c]);
        atomicAdd(&g_stats[64 + c], red2[c] + red2[64 + c] + red2[128 + c] + red2[192 + c]);
    }
}

// ---------------- pm triplet apply with fused x-BN ----------------
__global__ __launch_bounds__(256) void k_pm_apply(const float* __restrict__ bxw,
                                                  const float* __restrict__ bxb) {
    int lane = threadIdx.x & 31;
    int warp = (blockIdx.x * 256 + threadIdx.x) >> 5;
    int nwarp = (gridDim.x * 256) >> 5;

    const float invn = 1.f / NN;
    float m0 = g_stats[lane] * invn;
    float m1 = g_stats[lane + 32] * invn;
    float v0 = g_stats[64 + lane] * invn - m0 * m0;
    float v1 = g_stats[64 + lane + 32] * invn - m1 * m1;
    float sc0 = bxw[lane] * rsqrtf(v0 + BN_EPS);
    float sc1 = bxw[lane + 32] * rsqrtf(v1 + BN_EPS);
    float sh0 = bxb[lane] - m0 * sc0;
    float sh1 = bxb[lane + 32] - m1 * sc1;

    int cnt = g_cnt;
    if (cnt > TRIP_CAP) cnt = TRIP_CAP;
    for (int i = warp; i < cnt; i += nwarp) {
        int n = g_trip_n[i];
        int e = g_trip_e[i];
        float val = g_trip_v[i];
        float x0 = fmaf(g_x[(size_t)n * 64 + lane],      sc0, sh0);
        float x1 = fmaf(g_x[(size_t)n * 64 + lane + 32], sc1, sh1);
        atomicAdd(&g_pm_x[(size_t)e * 64 + lane],      val * x0);
        atomicAdd(&g_pm_x[(size_t)e * 64 + lane + 32], val * x1);
    }
}

// ---------------- y combine + concat/relu + BN stats -> out ----------------
__global__ __launch_bounds__(256) void k_y_linear(const float* __restrict__ gaw,
                                                  const float* __restrict__ gab,
                                                  const float* __restrict__ gxw,
                                                  const float* __restrict__ gxb,
                                                  const float* __restrict__ garw,
                                                  const float* __restrict__ garb,
                                                  const float* __restrict__ gxrw,
                                                  const float* __restrict__ gxrb,
                                                  float* __restrict__ out) {
    __shared__ float s_lg[16 * 64];
    __shared__ float s_pm[16 * 64];
    __shared__ float red[256], red2[256];
    int t = threadIdx.x;
    int rowbase = blockIdx.x * 16;
    reinterpret_cast<float4*>(s_lg)[t] =
        reinterpret_cast<const float4*>(g_lg_y + (size_t)rowbase * 64)[t];
    reinterpret_cast<float4*>(s_pm)[t] =
        reinterpret_cast<const float4*>(g_pm_x + (size_t)rowbase * 64)[t];
    __syncthreads();
    int c = t & 63, slot = t >> 6;
    const float *wa, *wx; float bias; bool dorelu;
    if (c < 32) { wa = gaw + c * 64;   wx = gxw + c * 64;
                  bias = gab[c] + gxb[c];            dorelu = false; }
    else        { int cr = c - 32;
                  wa = garw + cr * 64; wx = gxrw + cr * 64;
                  bias = garb[cr] + gxrb[cr];        dorelu = true;  }
    float acc[4] = {bias, bias, bias, bias};
    #pragma unroll
    for (int f = 0; f < 64; f += 4) {
        float4 wav = *reinterpret_cast<const float4*>(wa + f);
        float4 wxv = *reinterpret_cast<const float4*>(wx + f);
        #pragma unroll
        for (int j = 0; j < 4; ++j) {
            float4 pa = *reinterpret_cast<const float4*>(&s_lg[(slot + 4 * j) * 64 + f]);
            float4 px = *reinterpret_cast<const float4*>(&s_pm[(slot + 4 * j) * 64 + f]);
            float a = acc[j];
            a = fmaf(wav.x, pa.x, fmaf(wav.y, pa.y, fmaf(wav.z, pa.z, fmaf(wav.w, pa.w, a))));
            a = fmaf(wxv.x, px.x, fmaf(wxv.y, px.y, fmaf(wxv.z, px.z, fmaf(wxv.w, px.w, a))));
            acc[j] = a;
        }
    }
    float s = 0.f, sq = 0.f;
    #pragma unroll
    for (int j = 0; j < 4; ++j) {
        float v = acc[j];
        if (dorelu) v = fmaxf(v, 0.f);
        out[(size_t)(rowbase + slot + 4 * j) * 64 + c] = v;
        s += v; sq += v * v;
    }
    red[t] = s; red2[t] = sq;
    __syncthreads();
    if (slot == 0) {
        atomicAdd(&g_stats[128 + c], red[c] + red[64 + c] + red[128 + c] + red[192 + c]);
        atomicAdd(&g_stats[192 + c], red2[c] + red2[64 + c] + red2[128 + c] + red2[192 + c]);
    }
}

// ---------------- final BN on y (vectorized, in place) ----------------
__global__ __launch_bounds__(256) void k_bn_y(float4* __restrict__ buf,
                                              const float* __restrict__ w,
                                              const float* __restrict__ b) {
    int idx = blockIdx.x * 256 + threadIdx.x;   // EE*16 = 131072 float4s
    const float inve = 1.f / EE;
    int c0 = (idx & 15) << 2;
    float4 v = buf[idx];
    float* vp = reinterpret_cast<float*>(&v);
    #pragma unroll
    for (int j = 0; j < 4; ++j) {
        int c = c0 + j;
        float m = g_stats[128 + c] * inve;
        float var = g_stats[192 + c] * inve - m * m;
        float sc = w[c] * rsqrtf(var + BN_EPS);
        vp[j] = (vp[j] - m) * sc + b[c];
    }
    buf[idx] = v;
}

// ---------------- launch ----------------
extern "C" void kernel_launch(void* const* d_in, const int* in_sizes, int n_in,
                              void* d_out, int out_size) {
    const float* y    = (const float*)d_in[0];
    const float* lg   = (const float*)d_in[3];
    const float* pm   = (const float*)d_in[4];
    const float* pd   = (const float*)d_in[5];
    const float* tw   = (const float*)d_in[6];
    const float* tb   = (const float*)d_in[7];
    const float* trw  = (const float*)d_in[8];
    const float* trb  = (const float*)d_in[9];
    const float* gaw  = (const float*)d_in[10];
    const float* gab  = (const float*)d_in[11];
    const float* gxw  = (const float*)d_in[12];
    const float* gxb  = (const float*)d_in[13];
    const float* garw = (const float*)d_in[14];
    const float* garb = (const float*)d_in[15];
    const float* gxrw = (const float*)d_in[16];
    const float* gxrb = (const float*)d_in[17];
    const float* bxw  = (const float*)d_in[18];
    const float* bxb  = (const float*)d_in[19];
    const float* byw  = (const float*)d_in[20];
    const float* byb  = (const float*)d_in[21];
    float* out = (float*)d_out;

    // init pm_x / stats / counter
    k_init<<<512, 256>>>();
    // single full-chip 512MB scan: pd gather + lg gather + pm triplet extract
    k_megascan<<<2048, 256>>>(pd, lg, pm, y);
    // x linear + concat/relu + BN-x stats (x kept pre-BN)
    k_x_linear<<<NN / 16, 256>>>(tw, tb, trw, trb);
    // pm^T @ BN(x) via triplets (BN-x affine fused)
    k_pm_apply<<<128, 256>>>(bxw, bxb);
    // y combine + concat/relu + BN-y stats -> d_out (pre-BN)
    k_y_linear<<<EE / 16, 256>>>(gaw, gab, gxw, gxb, garw, garb, gxrw, gxrb, out);
    // BN-y in place, vectorized
    k_bn_y<<<512, 256>>>((float4*)out, byw, byb);
}

// round 3
// speedup vs baseline: 1.1148x; 1.0788x over previous
#include <cuda_runtime.h>
#include <cstdint>

#define NN 4096
#define EE 8192
#define FDIM 64
#define BN_EPS 1e-5f
#define TRIP_CAP 131072

// ---------------- device scratch ----------------
__device__ float g_pd_y[NN * FDIM];
__device__ float g_x[NN * FDIM];
__device__ float g_lg_y[EE * FDIM];
__device__ float g_pm_x[EE * FDIM];
__device__ float g_stats[256];
__device__ int   g_cnt;
__device__ int   g_trip_n[TRIP_CAP];
__device__ int   g_trip_e[TRIP_CAP];
__device__ float g_trip_v[TRIP_CAP];

// ---------------- init ----------------
__global__ __launch_bounds__(256) void k_init() {
    int idx = blockIdx.x * 256 + threadIdx.x;              // 512*256 = 131072
    reinterpret_cast<float4*>(g_pm_x)[idx] = make_float4(0.f, 0.f, 0.f, 0.f);
    if (idx < 256) g_stats[idx] = 0.f;
    if (idx == 0) g_cnt = 0;
}

// ---------------- helpers ----------------
__device__ __forceinline__ unsigned nz4(float4 v) {
    return __float_as_uint(v.x) | __float_as_uint(v.y) |
           __float_as_uint(v.z) | __float_as_uint(v.w);
}

__device__ __forceinline__ void gath_chunk(float4 v, unsigned ored, int colbase, int lane,
                                           const float* __restrict__ B,
                                           float& acc0, float& acc1) {
    unsigned mask = __ballot_sync(0xffffffffu, ored != 0u);
    while (mask) {
        int src = __ffs(mask) - 1;
        mask &= mask - 1;
        float b0 = __shfl_sync(0xffffffffu, v.x, src);
        float b1 = __shfl_sync(0xffffffffu, v.y, src);
        float b2 = __shfl_sync(0xffffffffu, v.z, src);
        float b3 = __shfl_sync(0xffffffffu, v.w, src);
        const float* bp = B + (size_t)(colbase + (src << 2)) * FDIM + lane;
        if (b0 != 0.f) { acc0 = fmaf(b0, bp[0],   acc0); acc1 = fmaf(b0, bp[32],  acc1); }
        if (b1 != 0.f) { acc0 = fmaf(b1, bp[64],  acc0); acc1 = fmaf(b1, bp[96],  acc1); }
        if (b2 != 0.f) { acc0 = fmaf(b2, bp[128], acc0); acc1 = fmaf(b2, bp[160], acc1); }
        if (b3 != 0.f) { acc0 = fmaf(b3, bp[192], acc0); acc1 = fmaf(b3, bp[224], acc1); }
    }
}

__device__ __forceinline__ void pm_emit(float4 v, int col0, int n) {
    int k = (v.x != 0.f) + (v.y != 0.f) + (v.z != 0.f) + (v.w != 0.f);
    if (!k) return;
    int pos = atomicAdd(&g_cnt, k);
    float vals[4] = {v.x, v.y, v.z, v.w};
    #pragma unroll
    for (int j = 0; j < 4; ++j) {
        if (vals[j] != 0.f && pos < TRIP_CAP) {
            g_trip_n[pos] = n;
            g_trip_e[pos] = col0 + j;
            g_trip_v[pos] = vals[j];
            ++pos;
        }
    }
}

// ---------------- mega-scan: 8-deep LDG.128 batches ----------------
// 16384 warps, one per 8192-float row. pd [0,4096), lg [4096,12288), pm [12288,16384)
__global__ __launch_bounds__(256) void k_megascan(const float* __restrict__ pd,
                                                  const float* __restrict__ lg,
                                                  const float* __restrict__ pm,
                                                  const float* __restrict__ y) {
    int gw = (blockIdx.x * 256 + threadIdx.x) >> 5;
    int lane = threadIdx.x & 31;

    const float4* arow;
    int mode, row;
    if (gw < NN)            { mode = 0; row = gw;           arow = reinterpret_cast<const float4*>(pd + (size_t)row * EE); }
    else if (gw < NN + EE)  { mode = 1; row = gw - NN;      arow = reinterpret_cast<const float4*>(lg + (size_t)row * EE); }
    else                    { mode = 2; row = gw - NN - EE; arow = reinterpret_cast<const float4*>(pm + (size_t)row * EE); }

    if (mode < 2) {
        float acc0 = 0.f, acc1 = 0.f;
        #pragma unroll 1
        for (int g = 0; g < EE / 1024; ++g) {            // 8 groups of 1024 floats
            int fb = (g << 8) + lane;                     // float4 index base
            float4 v[8];
            #pragma unroll
            for (int j = 0; j < 8; ++j) v[j] = __ldg(arow + fb + (j << 5));
            unsigned o[8]; unsigned any = 0;
            #pragma unroll
            for (int j = 0; j < 8; ++j) { o[j] = nz4(v[j]); any |= o[j]; }
            if (__ballot_sync(0xffffffffu, any != 0u)) {
                int cb = g << 10;
                #pragma unroll
                for (int j = 0; j < 8; ++j)
                    gath_chunk(v[j], o[j], cb + (j << 7), lane, y, acc0, acc1);
            }
        }
        float* out = (mode == 0 ? g_pd_y : g_lg_y) + (size_t)row * FDIM;
        out[lane]      = acc0;
        out[lane + 32] = acc1;
    } else {
        #pragma unroll 1
        for (int g = 0; g < EE / 1024; ++g) {
            int fb = (g << 8) + lane;
            float4 v[8];
            #pragma unroll
            for (int j = 0; j < 8; ++j) v[j] = __ldg(arow + fb + (j << 5));
            unsigned o[8]; unsigned any = 0;
            #pragma unroll
            for (int j = 0; j < 8; ++j) { o[j] = nz4(v[j]); any |= o[j]; }
            if (__ballot_sync(0xffffffffu, any != 0u)) {
                int cb = (g << 10) + (lane << 2);
                #pragma unroll
                for (int j = 0; j < 8; ++j)
                    if (o[j]) pm_emit(v[j], cb + (j << 7), row);
            }
        }
    }
}

// ---------------- x linear + concat/relu + BN-x stats ----------------
__global__ __launch_bounds__(256) void k_x_linear(const float* __restrict__ tw,
                                                  const float* __restrict__ tb,
                                                  const float* __restrict__ trw,
                                                  const float* __restrict__ trb) {
    __shared__ float s_in[16 * 64];
    __shared__ float red[256], red2[256];
    int t = threadIdx.x;
    int rowbase = blockIdx.x * 16;
    reinterpret_cast<float4*>(s_in)[t] =
        reinterpret_cast<const float4*>(g_pd_y + (size_t)rowbase * 64)[t];
    __syncthreads();
    int c = t & 63, slot = t >> 6;
    const float* w; float bias; bool dorelu;
    if (c < 32) { w = tw + c * 64;         bias = tb[c];        dorelu = false; }
    else        { w = trw + (c - 32) * 64; bias = trb[c - 32];  dorelu = true;  }
    float acc[4] = {bias, bias, bias, bias};
    #pragma unroll
    for (int f = 0; f < 64; f += 4) {
        float4 wv = *reinterpret_cast<const float4*>(w + f);
        #pragma unroll
        for (int j = 0; j < 4; ++j) {
            float4 pv = *reinterpret_cast<const float4*>(&s_in[(slot + 4 * j) * 64 + f]);
            acc[j] = fmaf(wv.x, pv.x, fmaf(wv.y, pv.y, fmaf(wv.z, pv.z, fmaf(wv.w, pv.w, acc[j]))));
        }
    }
    float s = 0.f, sq = 0.f;
    #pragma unroll
    for (int j = 0; j < 4; ++j) {
        float v = acc[j];
        if (dorelu) v = fmaxf(v, 0.f);
        g_x[(size_t)(rowbase + slot + 4 * j) * 64 + c] = v;
        s += v; sq += v * v;
    }
    red[t] = s; red2[t] = sq;
    __syncthreads();
    if (slot == 0) {
        atomicAdd(&g_stats[c],      red[c] + red[64 + c] + red[128 + c] + red[192 + c]);
        atomicAdd(&g_stats[64 + c], red2[c] + red2[64 + c] + red2[128 + c] + red2[192 + c]);
    }
}

// ---------------- pm triplet apply, fused x-BN: ONE triplet per warp ----------------
__global__ __launch_bounds__(256) void k_pm_apply(const float* __restrict__ bxw,
                                                  const float* __restrict__ bxb) {
    int lane = threadIdx.x & 31;
    int warp = (blockIdx.x * 256 + threadIdx.x) >> 5;   // 16384 warps

    int cnt = g_cnt;
    if (cnt > TRIP_CAP) cnt = TRIP_CAP;
    if (warp >= cnt) return;

    const float invn = 1.f / NN;
    float m0 = g_stats[lane] * invn;
    float m1 = g_stats[lane + 32] * invn;
    float v0 = g_stats[64 + lane] * invn - m0 * m0;
    float v1 = g_stats[64 + lane + 32] * invn - m1 * m1;
    float sc0 = bxw[lane] * rsqrtf(v0 + BN_EPS);
    float sc1 = bxw[lane + 32] * rsqrtf(v1 + BN_EPS);
    float sh0 = bxb[lane] - m0 * sc0;
    float sh1 = bxb[lane + 32] - m1 * sc1;

    for (int i = warp; i < cnt; i += 16384) {
        int n = g_trip_n[i];
        int e = g_trip_e[i];
        float val = g_trip_v[i];
        float x0 = fmaf(g_x[(size_t)n * 64 + lane],      sc0, sh0);
        float x1 = fmaf(g_x[(size_t)n * 64 + lane + 32], sc1, sh1);
        atomicAdd(&g_pm_x[(size_t)e * 64 + lane],      val * x0);
        atomicAdd(&g_pm_x[(size_t)e * 64 + lane + 32], val * x1);
    }
}

// ---------------- y combine + concat/relu + BN-y stats -> out ----------------
__global__ __launch_bounds__(256) void k_y_linear(const float* __restrict__ gaw,
                                                  const float* __restrict__ gab,
                                                  const float* __restrict__ gxw,
                                                  const float* __restrict__ gxb,
                                                  const float* __restrict__ garw,
                                                  const float* __restrict__ garb,
                                                  const float* __restrict__ gxrw,
                                                  const float* __restrict__ gxrb,
                                                  float* __restrict__ out) {
    __shared__ float s_lg[16 * 64];
    __shared__ float s_pm[16 * 64];
    __shared__ float red[256], red2[256];
    int t = threadIdx.x;
    int rowbase = blockIdx.x * 16;
    reinterpret_cast<float4*>(s_lg)[t] =
        reinterpret_cast<const float4*>(g_lg_y + (size_t)rowbase * 64)[t];
    reinterpret_cast<float4*>(s_pm)[t] =
        reinterpret_cast<const float4*>(g_pm_x + (size_t)rowbase * 64)[t];
    __syncthreads();
    int c = t & 63, slot = t >> 6;
    const float *wa, *wx; float bias; bool dorelu;
    if (c < 32) { wa = gaw + c * 64;   wx = gxw + c * 64;
                  bias = gab[c] + gxb[c];            dorelu = false; }
    else        { int cr = c - 32;
                  wa = garw + cr * 64; wx = gxrw + cr * 64;
                  bias = garb[cr] + gxrb[cr];        dorelu = true;  }
    float acc[4] = {bias, bias, bias, bias};
    #pragma unroll
    for (int f = 0; f < 64; f += 4) {
        float4 wav = *reinterpret_cast<const float4*>(wa + f);
        float4 wxv = *reinterpret_cast<const float4*>(wx + f);
        #pragma unroll
        for (int j = 0; j < 4; ++j) {
            float4 pa = *reinterpret_cast<const float4*>(&s_lg[(slot + 4 * j) * 64 + f]);
            float4 px = *reinterpret_cast<const float4*>(&s_pm[(slot + 4 * j) * 64 + f]);
            float a = acc[j];
            a = fmaf(wav.x, pa.x, fmaf(wav.y, pa.y, fmaf(wav.z, pa.z, fmaf(wav.w, pa.w, a))));
            a = fmaf(wxv.x, px.x, fmaf(wxv.y, px.y, fmaf(wxv.z, px.z, fmaf(wxv.w, px.w, a))));
            acc[j] = a;
        }
    }
    float s = 0.f, sq = 0.f;
    #pragma unroll
    for (int j = 0; j < 4; ++j) {
        float v = acc[j];
        if (dorelu) v = fmaxf(v, 0.f);
        out[(size_t)(rowbase + slot + 4 * j) * 64 + c] = v;
        s += v; sq += v * v;
    }
    red[t] = s; red2[t] = sq;
    __syncthreads();
    if (slot == 0) {
        atomicAdd(&g_stats[128 + c], red[c] + red[64 + c] + red[128 + c] + red[192 + c]);
        atomicAdd(&g_stats[192 + c], red2[c] + red2[64 + c] + red2[128 + c] + red2[192 + c]);
    }
}

// ---------------- final BN on y (vectorized, in place) ----------------
__global__ __launch_bounds__(256) void k_bn_y(float4* __restrict__ buf,
                                              const float* __restrict__ w,
                                              const float* __restrict__ b) {
    int idx = blockIdx.x * 256 + threadIdx.x;
    const float inve = 1.f / EE;
    int c0 = (idx & 15) << 2;
    float4 v = buf[idx];
    float* vp = reinterpret_cast<float*>(&v);
    #pragma unroll
    for (int j = 0; j < 4; ++j) {
        int c = c0 + j;
        float m = g_stats[128 + c] * inve;
        float var = g_stats[192 + c] * inve - m * m;
        float sc = w[c] * rsqrtf(var + BN_EPS);
        vp[j] = (vp[j] - m) * sc + b[c];
    }
    buf[idx] = v;
}

// ---------------- launch ----------------
extern "C" void kernel_launch(void* const* d_in, const int* in_sizes, int n_in,
                              void* d_out, int out_size) {
    const float* y    = (const float*)d_in[0];
    const float* lg   = (const float*)d_in[3];
    const float* pm   = (const float*)d_in[4];
    const float* pd   = (const float*)d_in[5];
    const float* tw   = (const float*)d_in[6];
    const float* tb   = (const float*)d_in[7];
    const float* trw  = (const float*)d_in[8];
    const float* trb  = (const float*)d_in[9];
    const float* gaw  = (const float*)d_in[10];
    const float* gab  = (const float*)d_in[11];
    const float* gxw  = (const float*)d_in[12];
    const float* gxb  = (const float*)d_in[13];
    const float* garw = (const float*)d_in[14];
    const float* garb = (const float*)d_in[15];
    const float* gxrw = (const float*)d_in[16];
    const float* gxrb = (const float*)d_in[17];
    const float* bxw  = (const float*)d_in[18];
    const float* bxb  = (const float*)d_in[19];
    const float* byw  = (const float*)d_in[20];
    const float* byb  = (const float*)d_in[21];
    float* out = (float*)d_out;

    k_init<<<512, 256>>>();
    k_megascan<<<2048, 256>>>(pd, lg, pm, y);
    k_x_linear<<<NN / 16, 256>>>(tw, tb, trw, trb);
    k_pm_apply<<<2048, 256>>>(bxw, bxb);
    k_y_linear<<<EE / 16, 256>>>(gaw, gab, gxw, gxb, garw, garb, gxrw, gxrb, out);
    k_bn_y<<<512, 256>>>((float4*)out, byw, byb);
}

// round 4
// speedup vs baseline: 1.1285x; 1.0123x over previous
#include <cuda_runtime.h>
#include <cstdint>

#define NN 4096
#define EE 8192
#define FDIM 64
#define BN_EPS 1e-5f
#define TRIP_CAP 131072
#define TOTROWS (NN + EE + NN)   // pd rows, lg rows, pm rows

// ---------------- device scratch ----------------
__device__ float g_pd_y[NN * FDIM];
__device__ float g_x[NN * FDIM];
__device__ float g_lg_y[EE * FDIM];
__device__ float g_pm_x[EE * FDIM];
__device__ float g_stats[256];
__device__ int   g_cnt;
__device__ unsigned g_row_ctr;
__device__ int   g_trip_n[TRIP_CAP];
__device__ int   g_trip_e[TRIP_CAP];
__device__ float g_trip_v[TRIP_CAP];

// ---------------- init ----------------
__global__ __launch_bounds__(256) void k_init() {
    int idx = blockIdx.x * 256 + threadIdx.x;              // 512*256 = 131072
    reinterpret_cast<float4*>(g_pm_x)[idx] = make_float4(0.f, 0.f, 0.f, 0.f);
    if (idx < 256) g_stats[idx] = 0.f;
    if (idx == 0) { g_cnt = 0; g_row_ctr = 0u; }
}

// ---------------- helpers ----------------
__device__ __forceinline__ unsigned nz4(float4 v) {
    return __float_as_uint(v.x) | __float_as_uint(v.y) |
           __float_as_uint(v.z) | __float_as_uint(v.w);
}

__device__ __forceinline__ void gath_chunk(float4 v, unsigned ored, int colbase, int lane,
                                           const float* __restrict__ B,
                                           float& acc0, float& acc1) {
    unsigned mask = __ballot_sync(0xffffffffu, ored != 0u);
    while (mask) {
        int src = __ffs(mask) - 1;
        mask &= mask - 1;
        float b0 = __shfl_sync(0xffffffffu, v.x, src);
        float b1 = __shfl_sync(0xffffffffu, v.y, src);
        float b2 = __shfl_sync(0xffffffffu, v.z, src);
        float b3 = __shfl_sync(0xffffffffu, v.w, src);
        const float* bp = B + (size_t)(colbase + (src << 2)) * FDIM + lane;
        if (b0 != 0.f) { acc0 = fmaf(b0, bp[0],   acc0); acc1 = fmaf(b0, bp[32],  acc1); }
        if (b1 != 0.f) { acc0 = fmaf(b1, bp[64],  acc0); acc1 = fmaf(b1, bp[96],  acc1); }
        if (b2 != 0.f) { acc0 = fmaf(b2, bp[128], acc0); acc1 = fmaf(b2, bp[160], acc1); }
        if (b3 != 0.f) { acc0 = fmaf(b3, bp[192], acc0); acc1 = fmaf(b3, bp[224], acc1); }
    }
}

__device__ __forceinline__ void pm_emit(float4 v, int col0, int n) {
    int k = (v.x != 0.f) + (v.y != 0.f) + (v.z != 0.f) + (v.w != 0.f);
    if (!k) return;
    int pos = atomicAdd(&g_cnt, k);
    float vals[4] = {v.x, v.y, v.z, v.w};
    #pragma unroll
    for (int j = 0; j < 4; ++j) {
        if (vals[j] != 0.f && pos < TRIP_CAP) {
            g_trip_n[pos] = n;
            g_trip_e[pos] = col0 + j;
            g_trip_v[pos] = vals[j];
            ++pos;
        }
    }
}

// ---------------- persistent mega-scan with dynamic row pop ----------------
// rows: pd [0,4096), lg [4096,12288), pm [12288,16384)
__global__ void __launch_bounds__(256, 5) k_megascan(const float* __restrict__ pd,
                                                     const float* __restrict__ lg,
                                                     const float* __restrict__ pm,
                                                     const float* __restrict__ y) {
    int lane = threadIdx.x & 31;
    while (true) {
        unsigned rowid;
        if (lane == 0) rowid = atomicAdd(&g_row_ctr, 1u);
        rowid = __shfl_sync(0xffffffffu, rowid, 0);
        if (rowid >= TOTROWS) return;

        const float4* arow;
        int mode, row;
        if (rowid < NN)            { mode = 0; row = (int)rowid;           arow = reinterpret_cast<const float4*>(pd + (size_t)row * EE); }
        else if (rowid < NN + EE)  { mode = 1; row = (int)rowid - NN;      arow = reinterpret_cast<const float4*>(lg + (size_t)row * EE); }
        else                       { mode = 2; row = (int)rowid - NN - EE; arow = reinterpret_cast<const float4*>(pm + (size_t)row * EE); }

        if (mode < 2) {
            float acc0 = 0.f, acc1 = 0.f;
            #pragma unroll 1
            for (int g = 0; g < EE / 512; ++g) {          // 16 groups of 512 floats
                int fb = (g << 7) + lane;
                float4 v0 = __ldcs(arow + fb);
                float4 v1 = __ldcs(arow + fb + 32);
                float4 v2 = __ldcs(arow + fb + 64);
                float4 v3 = __ldcs(arow + fb + 96);
                unsigned o0 = nz4(v0), o1 = nz4(v1), o2 = nz4(v2), o3 = nz4(v3);
                if (__ballot_sync(0xffffffffu, (o0 | o1 | o2 | o3) != 0u)) {
                    int cb = g << 9;
                    gath_chunk(v0, o0, cb,       lane, y, acc0, acc1);
                    gath_chunk(v1, o1, cb + 128, lane, y, acc0, acc1);
                    gath_chunk(v2, o2, cb + 256, lane, y, acc0, acc1);
                    gath_chunk(v3, o3, cb + 384, lane, y, acc0, acc1);
                }
            }
            float* out = (mode == 0 ? g_pd_y : g_lg_y) + (size_t)row * FDIM;
            out[lane]      = acc0;
            out[lane + 32] = acc1;
        } else {
            #pragma unroll 1
            for (int g = 0; g < EE / 512; ++g) {
                int fb = (g << 7) + lane;
                float4 v0 = __ldcs(arow + fb);
                float4 v1 = __ldcs(arow + fb + 32);
                float4 v2 = __ldcs(arow + fb + 64);
                float4 v3 = __ldcs(arow + fb + 96);
                unsigned o0 = nz4(v0), o1 = nz4(v1), o2 = nz4(v2), o3 = nz4(v3);
                if (__ballot_sync(0xffffffffu, (o0 | o1 | o2 | o3) != 0u)) {
                    int cb = (g << 9) + (lane << 2);
                    if (o0) pm_emit(v0, cb,       row);
                    if (o1) pm_emit(v1, cb + 128, row);
                    if (o2) pm_emit(v2, cb + 256, row);
                    if (o3) pm_emit(v3, cb + 384, row);
                }
            }
        }
    }
}

// ---------------- x linear + concat/relu + BN-x stats ----------------
__global__ __launch_bounds__(256) void k_x_linear(const float* __restrict__ tw,
                                                  const float* __restrict__ tb,
                                                  const float* __restrict__ trw,
                                                  const float* __restrict__ trb) {
    __shared__ float s_in[16 * 64];
    __shared__ float red[256], red2[256];
    int t = threadIdx.x;
    int rowbase = blockIdx.x * 16;
    reinterpret_cast<float4*>(s_in)[t] =
        reinterpret_cast<const float4*>(g_pd_y + (size_t)rowbase * 64)[t];
    __syncthreads();
    int c = t & 63, slot = t >> 6;
    const float* w; float bias; bool dorelu;
    if (c < 32) { w = tw + c * 64;         bias = tb[c];        dorelu = false; }
    else        { w = trw + (c - 32) * 64; bias = trb[c - 32];  dorelu = true;  }
    float acc[4] = {bias, bias, bias, bias};
    #pragma unroll
    for (int f = 0; f < 64; f += 4) {
        float4 wv = *reinterpret_cast<const float4*>(w + f);
        #pragma unroll
        for (int j = 0; j < 4; ++j) {
            float4 pv = *reinterpret_cast<const float4*>(&s_in[(slot + 4 * j) * 64 + f]);
            acc[j] = fmaf(wv.x, pv.x, fmaf(wv.y, pv.y, fmaf(wv.z, pv.z, fmaf(wv.w, pv.w, acc[j]))));
        }
    }
    float s = 0.f, sq = 0.f;
    #pragma unroll
    for (int j = 0; j < 4; ++j) {
        float v = acc[j];
        if (dorelu) v = fmaxf(v, 0.f);
        g_x[(size_t)(rowbase + slot + 4 * j) * 64 + c] = v;
        s += v; sq += v * v;
    }
    red[t] = s; red2[t] = sq;
    __syncthreads();
    if (slot == 0) {
        atomicAdd(&g_stats[c],      red[c] + red[64 + c] + red[128 + c] + red[192 + c]);
        atomicAdd(&g_stats[64 + c], red2[c] + red2[64 + c] + red2[128 + c] + red2[192 + c]);
    }
}

// ---------------- pm triplet apply, fused x-BN: one triplet per warp ----------------
__global__ __launch_bounds__(256) void k_pm_apply(const float* __restrict__ bxw,
                                                  const float* __restrict__ bxb) {
    int lane = threadIdx.x & 31;
    int warp = (blockIdx.x * 256 + threadIdx.x) >> 5;   // 16384 warps

    int cnt = g_cnt;
    if (cnt > TRIP_CAP) cnt = TRIP_CAP;
    if (warp >= cnt) return;

    const float invn = 1.f / NN;
    float m0 = g_stats[lane] * invn;
    float m1 = g_stats[lane + 32] * invn;
    float v0 = g_stats[64 + lane] * invn - m0 * m0;
    float v1 = g_stats[64 + lane + 32] * invn - m1 * m1;
    float sc0 = bxw[lane] * rsqrtf(v0 + BN_EPS);
    float sc1 = bxw[lane + 32] * rsqrtf(v1 + BN_EPS);
    float sh0 = bxb[lane] - m0 * sc0;
    float sh1 = bxb[lane + 32] - m1 * sc1;

    for (int i = warp; i < cnt; i += 16384) {
        int n = g_trip_n[i];
        int e = g_trip_e[i];
        float val = g_trip_v[i];
        float x0 = fmaf(g_x[(size_t)n * 64 + lane],      sc0, sh0);
        float x1 = fmaf(g_x[(size_t)n * 64 + lane + 32], sc1, sh1);
        atomicAdd(&g_pm_x[(size_t)e * 64 + lane],      val * x0);
        atomicAdd(&g_pm_x[(size_t)e * 64 + lane + 32], val * x1);
    }
}

// ---------------- y combine + concat/relu + BN-y stats -> out ----------------
__global__ __launch_bounds__(256) void k_y_linear(const float* __restrict__ gaw,
                                                  const float* __restrict__ gab,
                                                  const float* __restrict__ gxw,
                                                  const float* __restrict__ gxb,
                                                  const float* __restrict__ garw,
                                                  const float* __restrict__ garb,
                                                  const float* __restrict__ gxrw,
                                                  const float* __restrict__ gxrb,
                                                  float* __restrict__ out) {
    __shared__ float s_lg[16 * 64];
    __shared__ float s_pm[16 * 64];
    __shared__ float red[256], red2[256];
    int t = threadIdx.x;
    int rowbase = blockIdx.x * 16;
    reinterpret_cast<float4*>(s_lg)[t] =
        reinterpret_cast<const float4*>(g_lg_y + (size_t)rowbase * 64)[t];
    reinterpret_cast<float4*>(s_pm)[t] =
        reinterpret_cast<const float4*>(g_pm_x + (size_t)rowbase * 64)[t];
    __syncthreads();
    int c = t & 63, slot = t >> 6;
    const float *wa, *wx; float bias; bool dorelu;
    if (c < 32) { wa = gaw + c * 64;   wx = gxw + c * 64;
                  bias = gab[c] + gxb[c];            dorelu = false; }
    else        { int cr = c - 32;
                  wa = garw + cr * 64; wx = gxrw + cr * 64;
                  bias = garb[cr] + gxrb[cr];        dorelu = true;  }
    float acc[4] = {bias, bias, bias, bias};
    #pragma unroll
    for (int f = 0; f < 64; f += 4) {
        float4 wav = *reinterpret_cast<const float4*>(wa + f);
        float4 wxv = *reinterpret_cast<const float4*>(wx + f);
        #pragma unroll
        for (int j = 0; j < 4; ++j) {
            float4 pa = *reinterpret_cast<const float4*>(&s_lg[(slot + 4 * j) * 64 + f]);
            float4 px = *reinterpret_cast<const float4*>(&s_pm[(slot + 4 * j) * 64 + f]);
            float a = acc[j];
            a = fmaf(wav.x, pa.x, fmaf(wav.y, pa.y, fmaf(wav.z, pa.z, fmaf(wav.w, pa.w, a))));
            a = fmaf(wxv.x, px.x, fmaf(wxv.y, px.y, fmaf(wxv.z, px.z, fmaf(wxv.w, px.w, a))));
            acc[j] = a;
        }
    }
    float s = 0.f, sq = 0.f;
    #pragma unroll
    for (int j = 0; j < 4; ++j) {
        float v = acc[j];
        if (dorelu) v = fmaxf(v, 0.f);
        out[(size_t)(rowbase + slot + 4 * j) * 64 + c] = v;
        s += v; sq += v * v;
    }
    red[t] = s; red2[t] = sq;
    __syncthreads();
    if (slot == 0) {
        atomicAdd(&g_stats[128 + c], red[c] + red[64 + c] + red[128 + c] + red[192 + c]);
        atomicAdd(&g_stats[192 + c], red2[c] + red2[64 + c] + red2[128 + c] + red2[192 + c]);
    }
}

// ---------------- final BN on y (vectorized, in place) ----------------
__global__ __launch_bounds__(256) void k_bn_y(float4* __restrict__ buf,
                                              const float* __restrict__ w,
                                              const float* __restrict__ b) {
    int idx = blockIdx.x * 256 + threadIdx.x;
    const float inve = 1.f / EE;
    int c0 = (idx & 15) << 2;
    float4 v = buf[idx];
    float* vp = reinterpret_cast<float*>(&v);
    #pragma unroll
    for (int j = 0; j < 4; ++j) {
        int c = c0 + j;
        float m = g_stats[128 + c] * inve;
        float var = g_stats[192 + c] * inve - m * m;
        float sc = w[c] * rsqrtf(var + BN_EPS);
        vp[j] = (vp[j] - m) * sc + b[c];
    }
    buf[idx] = v;
}

// ---------------- launch ----------------
extern "C" void kernel_launch(void* const* d_in, const int* in_sizes, int n_in,
                              void* d_out, int out_size) {
    const float* y    = (const float*)d_in[0];
    const float* lg   = (const float*)d_in[3];
    const float* pm   = (const float*)d_in[4];
    const float* pd   = (const float*)d_in[5];
    const float* tw   = (const float*)d_in[6];
    const float* tb   = (const float*)d_in[7];
    const float* trw  = (const float*)d_in[8];
    const float* trb  = (const float*)d_in[9];
    const float* gaw  = (const float*)d_in[10];
    const float* gab  = (const float*)d_in[11];
    const float* gxw  = (const float*)d_in[12];
    const float* gxb  = (const float*)d_in[13];
    const float* garw = (const float*)d_in[14];
    const float* garb = (const float*)d_in[15];
    const float* gxrw = (const float*)d_in[16];
    const float* gxrb = (const float*)d_in[17];
    const float* bxw  = (const float*)d_in[18];
    const float* bxb  = (const float*)d_in[19];
    const float* byw  = (const float*)d_in[20];
    const float* byb  = (const float*)d_in[21];
    float* out = (float*)d_out;

    k_init<<<512, 256>>>();
    // persistent single-wave scan, dynamic row popping (740 = 148 SMs x 5 CTAs)
    k_megascan<<<740, 256>>>(pd, lg, pm, y);
    k_x_linear<<<NN / 16, 256>>>(tw, tb, trw, trb);
    k_pm_apply<<<2048, 256>>>(bxw, bxb);
    k_y_linear<<<EE / 16, 256>>>(gaw, gab, gxw, gxb, garw, garb, gxrw, gxrb, out);
    k_bn_y<<<512, 256>>>((float4*)out, byw, byb);
}